// round 2
// baseline (speedup 1.0000x reference)
#include <cuda_runtime.h>
#include <cuda_bf16.h>
#include <math.h>

// Problem constants (shapes fixed by the dataset)
#define NSEQ 4096
#define DIM  768
#define NH   8
#define HD   96
#define TD   2304         // 3*DIM
#define MAXB 2
#define SCALE 0.036084391824351615f   // 768^-0.5

// Scratch: [3][B*NH][NSEQ][HD]  (75.5 MB, static device array — allocation-guard safe)
__device__ float g_qkv[3ull * MAXB * NH * NSEQ * HD];

// ---------------------------------------------------------------------------
// Kernel 1: QKV GEMM.  C[8192,2304] = X[8192,768] @ W[768,2304] + bias,
// scattered into g_qkv as [s][b*NH+h][n][d].
// 64x64 tile, 256 threads, 4x4 per-thread register blocking, k-tile 16.
// ---------------------------------------------------------------------------
__global__ __launch_bounds__(256) void qkv_gemm_kernel(
    const float* __restrict__ X, const float* __restrict__ W,
    const float* __restrict__ bias, int B)
{
    __shared__ float As[16][68];   // As[kk][row]
    __shared__ float Ws[16][68];   // Ws[kk][col]

    const int tid = threadIdx.x;
    const int tx = tid & 15;       // 0..15
    const int ty = tid >> 4;       // 0..15
    const int row0 = blockIdx.y * 64;
    const int col0 = blockIdx.x * 64;

    float acc[4][4];
#pragma unroll
    for (int i = 0; i < 4; i++)
#pragma unroll
        for (int j = 0; j < 4; j++) acc[i][j] = 0.f;

    for (int k0 = 0; k0 < DIM; k0 += 16) {
        // load A tile (64 rows x 16 k), stored transposed As[kk][r]
#pragma unroll
        for (int t = tid; t < 64 * 16; t += 256) {
            int kk = t & 15, r = t >> 4;
            As[kk][r] = X[(size_t)(row0 + r) * DIM + k0 + kk];
        }
        // load W tile (16 k x 64 cols)
#pragma unroll
        for (int t = tid; t < 16 * 64; t += 256) {
            int c = t & 63, kk = t >> 6;
            Ws[kk][c] = W[(size_t)(k0 + kk) * TD + col0 + c];
        }
        __syncthreads();

#pragma unroll
        for (int kk = 0; kk < 16; kk++) {
            float a[4], bw[4];
#pragma unroll
            for (int i = 0; i < 4; i++) a[i] = As[kk][ty * 4 + i];
#pragma unroll
            for (int j = 0; j < 4; j++) bw[j] = Ws[kk][tx * 4 + j];
#pragma unroll
            for (int i = 0; i < 4; i++)
#pragma unroll
                for (int j = 0; j < 4; j++)
                    acc[i][j] = fmaf(a[i], bw[j], acc[i][j]);
        }
        __syncthreads();
    }

    // bias + scatter into g_qkv[s][b*NH+h][n][d]
    const size_t per_s = (size_t)B * NH * NSEQ * HD;
#pragma unroll
    for (int i = 0; i < 4; i++) {
        const int r = row0 + ty * 4 + i;
        const int b = r >> 12;          // /4096
        const int n = r & 4095;
#pragma unroll
        for (int j = 0; j < 4; j++) {
            const int c = col0 + tx * 4 + j;
            const float v = acc[i][j] + bias[c];
            const int s = c / DIM;
            const int rem = c - s * DIM;
            const int h = rem / HD;
            const int d = rem - h * HD;
            g_qkv[(size_t)s * per_s +
                  (((size_t)(b * NH + h)) * NSEQ + n) * HD + d] = v;
        }
    }
}

// ---------------------------------------------------------------------------
// Kernel 2: flash attention, fp32.
// grid = (NSEQ/64, B*NH), 256 threads, dynamic smem:
//   Qs[64][97], Ks[64][97], Vs[64][97], Ss[64][65]
// Each thread: 4x4 S-tile (phase 1), 4 rows x 6 cols of O (phase 2).
// ---------------------------------------------------------------------------
#define QSTR 97
#define SSTR 65
#define ATTN_SMEM_FLOATS (3 * 64 * QSTR + 64 * SSTR)
#define ATTN_SMEM_BYTES  (ATTN_SMEM_FLOATS * 4)

__global__ __launch_bounds__(256, 2) void attn_kernel(
    float* __restrict__ out, int B)
{
    extern __shared__ float smem[];
    float* Qs = smem;                    // 64*97
    float* Ks = Qs + 64 * QSTR;          // 64*97
    float* Vs = Ks + 64 * QSTR;          // 64*97
    float* Ss = Vs + 64 * QSTR;          // 64*65

    const int tid = threadIdx.x;
    const int tx = tid & 15;
    const int ty = tid >> 4;
    const int bh = blockIdx.y;
    const int q0 = blockIdx.x * 64;

    const size_t per_s = (size_t)B * NH * NSEQ * HD;
    const float* Qg = g_qkv + 0 * per_s + (size_t)bh * NSEQ * HD;
    const float* Kg = g_qkv + 1 * per_s + (size_t)bh * NSEQ * HD;
    const float* Vg = g_qkv + 2 * per_s + (size_t)bh * NSEQ * HD;

    // load Q tile once
    for (int t = tid; t < 64 * HD; t += 256) {
        int r = t / HD, d = t - r * HD;
        Qs[r * QSTR + d] = Qg[(size_t)(q0 + r) * HD + d];
    }

    float mrow[4], lrow[4], O[4][6];
#pragma unroll
    for (int i = 0; i < 4; i++) {
        mrow[i] = -INFINITY;
        lrow[i] = 0.f;
#pragma unroll
        for (int j = 0; j < 6; j++) O[i][j] = 0.f;
    }

    for (int kt = 0; kt < NSEQ; kt += 64) {
        // load K/V tiles
        for (int t = tid; t < 64 * HD; t += 256) {
            int r = t / HD, d = t - r * HD;
            Ks[r * QSTR + d] = Kg[(size_t)(kt + r) * HD + d];
            Vs[r * QSTR + d] = Vg[(size_t)(kt + r) * HD + d];
        }
        __syncthreads();

        // ---- phase 1: S = Q K^T * SCALE (4x4 per thread) ----
        float s[4][4];
#pragma unroll
        for (int i = 0; i < 4; i++)
#pragma unroll
            for (int j = 0; j < 4; j++) s[i][j] = 0.f;

#pragma unroll 8
        for (int d = 0; d < HD; d++) {
            float a[4], k4[4];
#pragma unroll
            for (int i = 0; i < 4; i++) a[i] = Qs[(ty * 4 + i) * QSTR + d];
#pragma unroll
            for (int j = 0; j < 4; j++) k4[j] = Ks[(tx * 4 + j) * QSTR + d];
#pragma unroll
            for (int i = 0; i < 4; i++)
#pragma unroll
                for (int j = 0; j < 4; j++)
                    s[i][j] = fmaf(a[i], k4[j], s[i][j]);
        }

        // ---- online softmax (rows owned by same ty group; 16-lane reduce) ----
#pragma unroll
        for (int i = 0; i < 4; i++) {
            float tmax = -INFINITY;
#pragma unroll
            for (int j = 0; j < 4; j++) {
                s[i][j] *= SCALE;
                tmax = fmaxf(tmax, s[i][j]);
            }
#pragma unroll
            for (int msk = 8; msk >= 1; msk >>= 1)
                tmax = fmaxf(tmax, __shfl_xor_sync(0xffffffffu, tmax, msk));

            const float mnew = fmaxf(mrow[i], tmax);
            float tsum = 0.f;
#pragma unroll
            for (int j = 0; j < 4; j++) {
                s[i][j] = __expf(s[i][j] - mnew);
                tsum += s[i][j];
            }
#pragma unroll
            for (int msk = 8; msk >= 1; msk >>= 1)
                tsum += __shfl_xor_sync(0xffffffffu, tsum, msk);

            const float corr = __expf(mrow[i] - mnew);   // 0 on first tile
            lrow[i] = lrow[i] * corr + tsum;
            mrow[i] = mnew;
#pragma unroll
            for (int j = 0; j < 6; j++) O[i][j] *= corr;

            // stage P into shared
#pragma unroll
            for (int j = 0; j < 4; j++)
                Ss[(ty * 4 + i) * SSTR + tx * 4 + j] = s[i][j];
        }
        __syncthreads();

        // ---- phase 2: O += P @ V (4 rows x 6 strided cols per thread) ----
#pragma unroll 4
        for (int kk = 0; kk < 64; kk++) {
            float pv[4], vv[6];
#pragma unroll
            for (int i = 0; i < 4; i++) pv[i] = Ss[(ty * 4 + i) * SSTR + kk];
#pragma unroll
            for (int j = 0; j < 6; j++) vv[j] = Vs[kk * QSTR + j * 16 + tx];
#pragma unroll
            for (int i = 0; i < 4; i++)
#pragma unroll
                for (int j = 0; j < 6; j++)
                    O[i][j] = fmaf(pv[i], vv[j], O[i][j]);
        }
        __syncthreads();   // before overwriting K/V/S next iteration
    }

    // epilogue: normalize, write out[b, n, h*96 + col]
    const int b = bh / NH;
    const int h = bh - b * NH;
#pragma unroll
    for (int i = 0; i < 4; i++) {
        const float inv = 1.f / lrow[i];
        const int n = q0 + ty * 4 + i;
        float* orow = out + ((size_t)b * NSEQ + n) * DIM + h * HD;
#pragma unroll
        for (int j = 0; j < 6; j++)
            orow[j * 16 + tx] = O[i][j] * inv;
    }
}

// ---------------------------------------------------------------------------
extern "C" void kernel_launch(void* const* d_in, const int* in_sizes, int n_in,
                              void* d_out, int out_size)
{
    const float* x    = (const float*)d_in[0];   // (B, N, 768)
    const float* Wqkv = (const float*)d_in[1];   // (768, 2304)
    const float* bqkv = (const float*)d_in[2];   // (2304,)
    float* out = (float*)d_out;

    const int B = in_sizes[0] / (NSEQ * DIM);

    // QKV projection + scatter
    {
        dim3 grid(TD / 64, (B * NSEQ) / 64);
        qkv_gemm_kernel<<<grid, 256>>>(x, Wqkv, bqkv, B);
    }

    // flash attention
    {
        cudaFuncSetAttribute(attn_kernel,
                             cudaFuncAttributeMaxDynamicSharedMemorySize,
                             ATTN_SMEM_BYTES);
        dim3 grid(NSEQ / 64, B * NH);
        attn_kernel<<<grid, 256, ATTN_SMEM_BYTES>>>(out, B);
    }
}